// round 13
// baseline (speedup 1.0000x reference)
#include <cuda_runtime.h>

#define NBOX   2000
#define MAXDET 10
#define TOPK   5
#define IMG_H  512
#define IMG_W  512
#define NIMG   16
#define CONF_T 0.2f
#define IOU_T  0.4f
#define TB     256
#define NCAND  64
#define BLK_PER_IMG 33     // 32 mask-slice blocks + 1 output block

// per-BLOCK fallback scratch (rare path) — no cross-block races
__device__ unsigned long long g_fbkey[NIMG * BLK_PER_IMG][NBOX];

__device__ __forceinline__ unsigned long long u64max(unsigned long long a, unsigned long long b) {
    return a > b ? a : b;
}

__global__ __launch_bounds__(TB)
void fused_kernel(const float* __restrict__ region,
                  const float* __restrict__ neg,
                  float* __restrict__ out_mask,
                  float* __restrict__ out_tbox,
                  float* __restrict__ out_keep2)
{
    const int bid = blockIdx.x;
    const int b   = bid / BLK_PER_IMG;          // image
    const int j   = bid - b * BLK_PER_IMG;      // 0..31 mask slices, 32 = output block
    const int tid = threadIdx.x;
    const int wid = tid >> 5;
    const int lid = tid & 31;
    const float* rb = region + (long)b * NBOX * 5;

    __shared__ float s_conf[NBOX];
    __shared__ float s_neg[MAXDET * 5];
    __shared__ int s_hist[13];
    __shared__ float s_T;
    __shared__ int s_fb, s_complete, s_hasconf, s_ncand, s_pcnt;
    __shared__ unsigned long long s_ck[NCAND];
    __shared__ float4 s_cbox[NCAND];
    __shared__ unsigned long long s_skey[NCAND];
    __shared__ float4 s_sbox[NCAND];
    __shared__ unsigned long long s_sup[NCAND];
    __shared__ unsigned char s_tinyb[NCAND];
    __shared__ unsigned long long s_wmax[8];
    __shared__ unsigned long long s_win;
    __shared__ float4 s_pk[MAXDET];
    __shared__ float  s_pkcf[MAXDET];
    __shared__ float s_cb[MAXDET * 5];
    __shared__ int   s_ord[MAXDET];
    __shared__ float s_sc[MAXDET * 5];
    __shared__ unsigned s_supE[MAXDET];
    __shared__ unsigned s_keepmask;
    __shared__ int4 s_rect[MAXDET];

    const float LAD[13] = {0.991f, 0.9865f, 0.980f, 0.970f, 0.954f, 0.932f,
                           0.897f, 0.846f, 0.769f, 0.654f, 0.481f, 0.221f, CONF_T};

    if (tid < 13) s_hist[tid] = 0;
    if (tid == 0) { s_fb = 0; s_complete = 0; s_hasconf = 0; s_ncand = 0; s_pcnt = 0; }
    if (tid < MAXDET * 5) s_neg[tid] = neg[b * MAXDET * 5 + tid];
    __syncthreads();

    // ---- phase 1: stream confs (global->smem) + ballot histogram ----
    for (int base = 0; base < 2048; base += TB) {
        int i = base + tid;
        float cf = -1.0f;
        if (i < NBOX) { cf = rb[i * 5 + 4]; s_conf[i] = cf; }
        bool valid = (cf > CONF_T);
        unsigned anyb = __ballot_sync(0xFFFFFFFFu, valid);
        if (anyb && lid == 0) s_hasconf = 1;
        int bk = -1;
        if (valid) {
            bk = 12;
            #pragma unroll
            for (int k = 11; k >= 0; k--) if (cf > LAD[k]) bk = k;
        }
        #pragma unroll
        for (int k = 0; k < 13; k++) {
            unsigned mm = __ballot_sync(0xFFFFFFFFu, bk == k);
            if (lid == 0 && mm) atomicAdd(&s_hist[k], __popc(mm));
        }
    }
    __syncthreads();

    // ---- phase 2: choose threshold ----
    if (tid == 0) {
        if (!s_hasconf) { s_fb = 1; s_T = 2.0f; }
        else {
            int suf = 0, prev = 0, chosen = -1, complete = 0, crossed = 0;
            for (int k = 0; k < 13; k++) {
                prev = suf; suf += s_hist[k];
                if (suf >= 24) {
                    crossed = 1;
                    if (suf <= NCAND) { chosen = k; complete = (k == 12); }
                    else if (k > 0 && prev >= 12) { chosen = k - 1; }
                    break;
                }
            }
            if (!crossed) { chosen = 12; complete = 1; }
            if (chosen < 0) { s_fb = 1; s_T = 2.0f; }
            else { s_T = LAD[chosen]; s_complete = complete; }
        }
    }
    __syncthreads();

    // ---- phase 3: compact candidates (conf from smem, coords from L2) ----
    {
        float T = s_T;
        for (int i = tid; i < NBOX; i += TB) {
            float cf = s_conf[i];
            if (cf > T) {
                int p = atomicAdd(&s_ncand, 1);
                if (p < NCAND) {
                    s_ck[p] = ((unsigned long long)__float_as_uint(cf) << 32)
                            | (unsigned long long)(0xFFFFFFFFu - (unsigned)i);
                    s_cbox[p] = make_float4(rb[i*5+0], rb[i*5+1], rb[i*5+2], rb[i*5+3]);
                }
            }
        }
    }
    __syncthreads();

    int nc = min(s_ncand, NCAND);

    // ---- phase 4: rank sort (keys distinct -> canonical order) ----
    if (tid < NCAND) {
        unsigned long long mykey = (tid < nc) ? s_ck[tid] : 0ULL;
        int rank = 0;
        for (int jj = 0; jj < nc; jj++) rank += (s_ck[jj] > mykey) ? 1 : 0;
        if (tid < nc) {
            s_skey[rank] = mykey;
            float4 bb = s_cbox[tid];
            s_sbox[rank]  = bb;
            s_tinyb[rank] = (bb.z - bb.x >= 1.0f && bb.w - bb.y >= 1.0f) ? 1 : 0;
        }
    }
    __syncthreads();

    // ---- phase 5: suppression matrix in sorted space (ballot rows, div-skip) ----
    for (int t = wid; t < 2 * nc; t += 8) {
        int row = t >> 1, colbase = (t & 1) << 5;
        bool bit = false;
        {
            float4 bi = s_sbox[row];
            float ai = fmaxf(bi.z - bi.x, 0.f) * fmaxf(bi.w - bi.y, 0.f);
            int col = colbase + lid;
            if (col < nc) {
                float4 bj = s_sbox[col];
                float ix1 = fmaxf(bi.x, bj.x), iy1 = fmaxf(bi.y, bj.y);
                float ix2 = fminf(bi.z, bj.z), iy2 = fminf(bi.w, bj.w);
                float inter = fmaxf(ix2 - ix1, 0.f) * fmaxf(iy2 - iy1, 0.f);
                if (inter > 0.f) {
                    float aj  = fmaxf(bj.z - bj.x, 0.f) * fmaxf(bj.w - bj.y, 0.f);
                    float iou = inter / (ai + aj - inter + 1e-9f);
                    bit = (iou > IOU_T);
                }
            }
        }
        unsigned mm = __ballot_sync(0xFFFFFFFFu, bit);
        if (lid == 0) ((unsigned*)s_sup)[t] = mm;
    }
    // zero remaining rows' masks not needed: greedy only touches rows < nc
    __syncthreads();

    // ---- phase 6: ffs-driven greedy scan (tid 0) ----
    if (tid == 0 && !s_fb) {
        if (s_ncand > NCAND) s_fb = 1;
        else {
            int pcnt = 0;
            unsigned long long alive = (nc >= 64) ? ~0ULL : ((1ULL << nc) - 1ULL);
            while (alive && pcnt < MAXDET) {
                int s = __ffsll((long long)alive) - 1;
                alive &= ~s_sup[s];
                alive &= ~(1ULL << s);
                if (s_tinyb[s]) {
                    s_pk[pcnt]   = s_sbox[s];
                    s_pkcf[pcnt] = __uint_as_float((unsigned)(s_skey[s] >> 32));
                    pcnt++;
                }
            }
            s_pcnt = pcnt;
            if (pcnt < MAXDET && !s_complete) s_fb = 1;
        }
    }
    __syncthreads();

    if (s_fb) {
        // ===== FALLBACK: iterative-argmax greedy NMS (per-block global scratch) =====
        const bool  hasconf = (s_hasconf != 0);
        const int   cap  = hasconf ? MAXDET : TOPK;
        const float thr0 = hasconf ? CONF_T : 0.0f;
        unsigned long long* fk = g_fbkey[bid];

        for (int i = tid; i < NBOX; i += TB) {
            float cf = s_conf[i];
            fk[i] = (cf > thr0)
                ? (((unsigned long long)__float_as_uint(cf) << 32)
                   | (unsigned long long)(0xFFFFFFFFu - (unsigned)i))
                : 0ULL;
        }
        __syncthreads();

        int   oi  = -1;
        float x1i = -1e9f, y1i = -1e9f, x2i = -1e9f, y2i = -1e9f, ai = 0.0f;
        int   cnt = 0;

        while (true) {
            unsigned long long part = 0ULL;
            for (int jj = tid; jj < NBOX; jj += TB) {
                unsigned long long k = fk[jj];
                if (!k) continue;
                if (jj == oi) { fk[jj] = 0ULL; continue; }
                float x1j = rb[jj*5+0], y1j = rb[jj*5+1];
                float x2j = rb[jj*5+2], y2j = rb[jj*5+3];
                float ix1 = fmaxf(x1i, x1j), iy1 = fmaxf(y1i, y1j);
                float ix2 = fminf(x2i, x2j), iy2 = fminf(y2i, y2j);
                float inter = fmaxf(ix2 - ix1, 0.0f) * fmaxf(iy2 - iy1, 0.0f);
                bool kill = false;
                if (inter > 0.f) {
                    float aj  = fmaxf(x2j - x1j, 0.0f) * fmaxf(y2j - y1j, 0.0f);
                    float iou = inter / (ai + aj - inter + 1e-9f);
                    kill = (iou > IOU_T);
                }
                if (kill) fk[jj] = 0ULL;
                else      part = u64max(part, k);
            }
            #pragma unroll
            for (int off = 16; off; off >>= 1)
                part = u64max(part, __shfl_down_sync(0xFFFFFFFFu, part, off));
            if (lid == 0) s_wmax[wid] = part;
            __syncthreads();
            if (wid == 0) {
                unsigned long long m = (lid < 8) ? s_wmax[lid] : 0ULL;
                #pragma unroll
                for (int off = 4; off; off >>= 1)
                    m = u64max(m, __shfl_down_sync(0xFFFFFFFFu, m, off));
                if (lid == 0) s_win = m;
            }
            __syncthreads();
            unsigned long long win = s_win;
            if (win == 0ULL) break;

            oi = (int)(0xFFFFFFFFu - (unsigned)(win & 0xFFFFFFFFull));
            x1i = rb[oi*5+0]; y1i = rb[oi*5+1];
            x2i = rb[oi*5+2]; y2i = rb[oi*5+3];
            ai = fmaxf(x2i - x1i, 0.0f) * fmaxf(y2i - y1i, 0.0f);
            if (x2i - x1i >= 1.0f && y2i - y1i >= 1.0f) {
                if (tid == 0) {
                    s_pk[cnt]   = make_float4(x1i, y1i, x2i, y2i);
                    s_pkcf[cnt] = __uint_as_float((unsigned)(win >> 32));
                }
                cnt++;
                if (cnt >= cap) break;
            }
        }
        if (tid == 0) s_pcnt = cnt;
        __syncthreads();
    }

    // ======================= PARALLEL EPILOGUE (all blocks) =======================
    if (tid < MAXDET) {
        if (tid < s_pcnt) {
            float4 bb = s_pk[tid];
            s_cb[tid*5+0] = bb.x; s_cb[tid*5+1] = bb.y;
            s_cb[tid*5+2] = bb.z; s_cb[tid*5+3] = bb.w;
            s_cb[tid*5+4] = s_pkcf[tid];
        } else {
            #pragma unroll
            for (int f = 0; f < 5; f++) s_cb[tid*5+f] = s_neg[tid*5+f];
        }
    }
    __syncthreads();
    if (tid < MAXDET) {
        float c = s_cb[tid*5+4];
        int rank = 0;
        #pragma unroll
        for (int jj = 0; jj < MAXDET; jj++) {
            float cj = s_cb[jj*5+4];
            rank += (cj > c || (cj == c && jj < tid)) ? 1 : 0;
        }
        s_ord[rank] = tid;
    }
    __syncthreads();
    if (tid < MAXDET) {
        int src = s_ord[tid];
        #pragma unroll
        for (int f = 0; f < 5; f++) s_sc[tid*5+f] = s_cb[src*5+f];
    }
    __syncthreads();
    if (tid < MAXDET) {
        float x1 = s_sc[tid*5+0], y1 = s_sc[tid*5+1];
        float x2 = s_sc[tid*5+2], y2 = s_sc[tid*5+3];
        float aa = fmaxf(x2 - x1, 0.f) * fmaxf(y2 - y1, 0.f);
        unsigned m = 0;
        for (int jj = tid + 1; jj < MAXDET; jj++) {
            float ix1 = fmaxf(x1, s_sc[jj*5+0]);
            float iy1 = fmaxf(y1, s_sc[jj*5+1]);
            float ix2 = fminf(x2, s_sc[jj*5+2]);
            float iy2 = fminf(y2, s_sc[jj*5+3]);
            float inter = fmaxf(ix2 - ix1, 0.f) * fmaxf(iy2 - iy1, 0.f);
            if (inter > 0.f) {
                float aj = fmaxf(s_sc[jj*5+2]-s_sc[jj*5+0],0.f) * fmaxf(s_sc[jj*5+3]-s_sc[jj*5+1],0.f);
                float iou = inter / (aa + aj - inter + 1e-9f);
                if (iou > IOU_T) m |= (1u << jj);
            }
        }
        s_supE[tid] = m;
    }
    __syncthreads();
    if (tid == 0) {
        unsigned alive = 0;
        for (int s = 0; s < MAXDET; s++) if (s_sc[s*5+4] > 0.0f) alive |= (1u << s);
        unsigned keepm = 0;
        for (int s = 0; s < MAXDET; s++) {
            if ((alive >> s) & 1u) { keepm |= (1u << s); alive &= ~s_supE[s]; }
        }
        s_keepmask = keepm;
    }
    __syncthreads();
    if (tid < MAXDET) {
        int k2 = (s_keepmask >> tid) & 1;
        int4 r;
        if (k2) {
            r.x = (int)floorf(s_sc[tid*5+0] + 0.5f);
            r.y = (int)floorf(s_sc[tid*5+1] + 0.5f);
            r.z = (int)floorf(s_sc[tid*5+2] + 0.5f);
            r.w = (int)floorf(s_sc[tid*5+3] + 0.5f);
        } else {
            r.x = 0; r.y = 0; r.z = 0; r.w = 0;   // y < r.w never true
        }
        s_rect[tid] = r;
    }
    __syncthreads();

    if (j == 32) {
        // ---- output block: tbox + keep2 ----
        if (tid < MAXDET) {
            int k2 = (s_keepmask >> tid) & 1;
            float* tb = out_tbox + b * (MAXDET * 4);
            #pragma unroll
            for (int f = 0; f < 4; f++)
                tb[tid*4+f] = k2 ? s_sc[tid*5+f] : 0.0f;
            out_keep2[b * MAXDET + tid] = k2 ? 1.0f : 0.0f;
        }
        return;
    }

    // ---- mask slice: 16 rows starting at j*16 ----
    {
        const int base_px = j * (16 * IMG_W);        // 8192 px per slice
        #pragma unroll
        for (int pass = 0; pass < 2; pass++) {
            int t   = base_px + (pass * TB + tid) * 16;
            int y   = t >> 9;
            int x0  = t & (IMG_W - 1);
            unsigned cover = 0;
            #pragma unroll
            for (int s = 0; s < MAXDET; s++) {
                int4 rr = s_rect[s];
                if (y >= rr.y && y < rr.w) {
                    int st = max(rr.x - x0, 0);
                    int en = min(rr.z - x0, 16);
                    if (en > st) cover |= ((1u << en) - (1u << st));
                }
            }
            float m[16];
            #pragma unroll
            for (int c = 0; c < 16; c++) m[c] = (cover >> c & 1u) ? 0.f : 1.f;

            float* dst = out_mask + ((long)b << 18) + t;
            asm volatile("st.global.v8.f32 [%0], {%1,%2,%3,%4,%5,%6,%7,%8};"
                         :: "l"(dst),
                            "f"(m[0]), "f"(m[1]), "f"(m[2]), "f"(m[3]),
                            "f"(m[4]), "f"(m[5]), "f"(m[6]), "f"(m[7]) : "memory");
            asm volatile("st.global.v8.f32 [%0], {%1,%2,%3,%4,%5,%6,%7,%8};"
                         :: "l"(dst + 8),
                            "f"(m[8]),  "f"(m[9]),  "f"(m[10]), "f"(m[11]),
                            "f"(m[12]), "f"(m[13]), "f"(m[14]), "f"(m[15]) : "memory");
        }
    }
}

extern "C" void kernel_launch(void* const* d_in, const int* in_sizes, int n_in,
                              void* d_out, int out_size)
{
    const float* region = nullptr;
    const float* neg    = nullptr;
    for (int i = 0; i < n_in; i++) {
        if (in_sizes[i] == NIMG * NBOX * 5)        region = (const float*)d_in[i];
        else if (in_sizes[i] == NIMG * MAXDET * 5) neg    = (const float*)d_in[i];
    }

    float* out      = (float*)d_out;
    float* out_mask = out;
    float* out_tbox = out + (long)NIMG * IMG_H * IMG_W;
    float* out_k2   = out_tbox + NIMG * MAXDET * 4;

    fused_kernel<<<NIMG * BLK_PER_IMG, TB>>>(region, neg, out_mask, out_tbox, out_k2);
}

// round 15
// speedup vs baseline: 1.6737x; 1.6737x over previous
#include <cuda_runtime.h>

#define NBOX   2000
#define MAXDET 10
#define TOPK   5
#define IMG_H  512
#define IMG_W  512
#define NIMG   16
#define CONF_T 0.2f
#define IOU_T  0.4f
#define FIX_T  0.98f
#define TB     256
#define NCAND  64
#define BLK_PER_IMG 33     // 32 mask-slice blocks + 1 output block

// per-BLOCK fallback scratch (rare path) — no cross-block races
__device__ unsigned long long g_fbkey[NIMG * BLK_PER_IMG][NBOX];

__device__ __forceinline__ unsigned long long u64max(unsigned long long a, unsigned long long b) {
    return a > b ? a : b;
}

__global__ __launch_bounds__(TB)
void fused_kernel(const float* __restrict__ region,
                  const float* __restrict__ neg,
                  float* __restrict__ out_mask,
                  float* __restrict__ out_tbox,
                  float* __restrict__ out_keep2)
{
    const int bid = blockIdx.x;
    const int b   = bid / BLK_PER_IMG;          // image
    const int j   = bid - b * BLK_PER_IMG;      // 0..31 mask slices, 32 = output block
    const int tid = threadIdx.x;
    const int wid = tid >> 5;
    const int lid = tid & 31;
    const float* rb = region + (long)b * NBOX * 5;

    __shared__ float s_neg[MAXDET * 5];
    __shared__ int s_fb, s_hasconf, s_ncand, s_pcnt;
    __shared__ unsigned long long s_ck[NCAND];
    __shared__ float4 s_cbox[NCAND];
    __shared__ unsigned long long s_skey[NCAND];
    __shared__ float4 s_sbox[NCAND];
    __shared__ unsigned long long s_sup[NCAND];
    __shared__ unsigned char s_tinyb[NCAND];
    __shared__ unsigned long long s_wmax[8];
    __shared__ unsigned long long s_win;
    __shared__ float4 s_pk[MAXDET];
    __shared__ float  s_pkcf[MAXDET];
    __shared__ float s_cb[MAXDET * 5];
    __shared__ int   s_ord[MAXDET];
    __shared__ float s_sc[MAXDET * 5];
    __shared__ unsigned s_supE[MAXDET];
    __shared__ unsigned s_keepmask;
    __shared__ int4 s_rect[MAXDET];

    if (tid == 0) { s_fb = 0; s_hasconf = 0; s_ncand = 0; s_pcnt = 0; }
    if (tid < MAXDET * 5) s_neg[tid] = neg[b * MAXDET * 5 + tid];
    __syncthreads();

    // ---- phase 1: single sweep — compact candidates with conf > FIX_T ----
    {
        int local_has = 0;
        #pragma unroll
        for (int base = 0; base < 2048; base += TB) {
            int i = base + tid;
            if (i < NBOX) {
                float cf = rb[i * 5 + 4];
                if (cf > CONF_T) local_has = 1;
                if (cf > FIX_T) {
                    int p = atomicAdd(&s_ncand, 1);
                    if (p < NCAND) {
                        s_ck[p] = ((unsigned long long)__float_as_uint(cf) << 32)
                                | (unsigned long long)(0xFFFFFFFFu - (unsigned)i);
                        s_cbox[p] = make_float4(rb[i*5+0], rb[i*5+1], rb[i*5+2], rb[i*5+3]);
                    }
                }
            }
        }
        if (local_has) s_hasconf = 1;    // benign race: all writers store 1
    }
    __syncthreads();

    int nc = min(s_ncand, NCAND);

    // ---- phase 2: rank sort (keys distinct -> canonical descending order) ----
    if (tid < NCAND) {
        unsigned long long mykey = (tid < nc) ? s_ck[tid] : 0ULL;
        int rank = 0;
        for (int jj = 0; jj < nc; jj++) rank += (s_ck[jj] > mykey) ? 1 : 0;
        if (tid < nc) {
            s_skey[rank] = mykey;
            float4 bb = s_cbox[tid];
            s_sbox[rank]  = bb;
            s_tinyb[rank] = (bb.z - bb.x >= 1.0f && bb.w - bb.y >= 1.0f) ? 1 : 0;
        }
    }
    __syncthreads();

    // ---- phase 3: suppression matrix in sorted space (ballot rows, div-skip) ----
    for (int t = wid; t < 2 * nc; t += 8) {
        int row = t >> 1, colbase = (t & 1) << 5;
        bool bit = false;
        {
            float4 bi = s_sbox[row];
            float ai = fmaxf(bi.z - bi.x, 0.f) * fmaxf(bi.w - bi.y, 0.f);
            int col = colbase + lid;
            if (col < nc) {
                float4 bj = s_sbox[col];
                float ix1 = fmaxf(bi.x, bj.x), iy1 = fmaxf(bi.y, bj.y);
                float ix2 = fminf(bi.z, bj.z), iy2 = fminf(bi.w, bj.w);
                float inter = fmaxf(ix2 - ix1, 0.f) * fmaxf(iy2 - iy1, 0.f);
                if (inter > 0.f) {
                    float aj  = fmaxf(bj.z - bj.x, 0.f) * fmaxf(bj.w - bj.y, 0.f);
                    float iou = inter / (ai + aj - inter + 1e-9f);
                    bit = (iou > IOU_T);
                }
            }
        }
        unsigned mm = __ballot_sync(0xFFFFFFFFu, bit);
        if (lid == 0) ((unsigned*)s_sup)[t] = mm;
    }
    __syncthreads();

    // ---- phase 4: ffs-driven greedy scan (tid 0) ----
    if (tid == 0) {
        if (s_ncand > NCAND) s_fb = 1;
        else {
            int pcnt = 0;
            unsigned long long alive = (nc >= 64) ? ~0ULL : ((1ULL << nc) - 1ULL);
            while (alive && pcnt < MAXDET) {
                int s = __ffsll((long long)alive) - 1;
                alive &= ~s_sup[s];
                alive &= ~(1ULL << s);
                if (s_tinyb[s]) {
                    s_pk[pcnt]   = s_sbox[s];
                    s_pkcf[pcnt] = __uint_as_float((unsigned)(s_skey[s] >> 32));
                    pcnt++;
                }
            }
            s_pcnt = pcnt;
            if (pcnt < MAXDET) s_fb = 1;   // fixed T never "complete": must fall back
        }
    }
    __syncthreads();

    if (s_fb) {
        // ===== FALLBACK: exact iterative-argmax greedy NMS (per-block global scratch) =====
        const bool  hasconf = (s_hasconf != 0);
        const int   cap  = hasconf ? MAXDET : TOPK;
        const float thr0 = hasconf ? CONF_T : 0.0f;
        unsigned long long* fk = g_fbkey[bid];

        for (int i = tid; i < NBOX; i += TB) {
            float cf = rb[i * 5 + 4];
            fk[i] = (cf > thr0)
                ? (((unsigned long long)__float_as_uint(cf) << 32)
                   | (unsigned long long)(0xFFFFFFFFu - (unsigned)i))
                : 0ULL;
        }
        __syncthreads();

        int   oi  = -1;
        float x1i = -1e9f, y1i = -1e9f, x2i = -1e9f, y2i = -1e9f, ai = 0.0f;
        int   cnt = 0;

        while (true) {
            unsigned long long part = 0ULL;
            for (int jj = tid; jj < NBOX; jj += TB) {
                unsigned long long k = fk[jj];
                if (!k) continue;
                if (jj == oi) { fk[jj] = 0ULL; continue; }
                float x1j = rb[jj*5+0], y1j = rb[jj*5+1];
                float x2j = rb[jj*5+2], y2j = rb[jj*5+3];
                float ix1 = fmaxf(x1i, x1j), iy1 = fmaxf(y1i, y1j);
                float ix2 = fminf(x2i, x2j), iy2 = fminf(y2i, y2j);
                float inter = fmaxf(ix2 - ix1, 0.0f) * fmaxf(iy2 - iy1, 0.0f);
                bool kill = false;
                if (inter > 0.f) {
                    float aj  = fmaxf(x2j - x1j, 0.0f) * fmaxf(y2j - y1j, 0.0f);
                    float iou = inter / (ai + aj - inter + 1e-9f);
                    kill = (iou > IOU_T);
                }
                if (kill) fk[jj] = 0ULL;
                else      part = u64max(part, k);
            }
            #pragma unroll
            for (int off = 16; off; off >>= 1)
                part = u64max(part, __shfl_down_sync(0xFFFFFFFFu, part, off));
            if (lid == 0) s_wmax[wid] = part;
            __syncthreads();
            if (wid == 0) {
                unsigned long long m = (lid < 8) ? s_wmax[lid] : 0ULL;
                #pragma unroll
                for (int off = 4; off; off >>= 1)
                    m = u64max(m, __shfl_down_sync(0xFFFFFFFFu, m, off));
                if (lid == 0) s_win = m;
            }
            __syncthreads();
            unsigned long long win = s_win;
            if (win == 0ULL) break;

            oi = (int)(0xFFFFFFFFu - (unsigned)(win & 0xFFFFFFFFull));
            x1i = rb[oi*5+0]; y1i = rb[oi*5+1];
            x2i = rb[oi*5+2]; y2i = rb[oi*5+3];
            ai = fmaxf(x2i - x1i, 0.0f) * fmaxf(y2i - y1i, 0.0f);
            if (x2i - x1i >= 1.0f && y2i - y1i >= 1.0f) {
                if (tid == 0) {
                    s_pk[cnt]   = make_float4(x1i, y1i, x2i, y2i);
                    s_pkcf[cnt] = __uint_as_float((unsigned)(win >> 32));
                }
                cnt++;
                if (cnt >= cap) break;
            }
        }
        if (tid == 0) s_pcnt = cnt;
        __syncthreads();
    }

    // ======================= PARALLEL EPILOGUE (all blocks) =======================
    if (tid < MAXDET) {
        if (tid < s_pcnt) {
            float4 bb = s_pk[tid];
            s_cb[tid*5+0] = bb.x; s_cb[tid*5+1] = bb.y;
            s_cb[tid*5+2] = bb.z; s_cb[tid*5+3] = bb.w;
            s_cb[tid*5+4] = s_pkcf[tid];
        } else {
            #pragma unroll
            for (int f = 0; f < 5; f++) s_cb[tid*5+f] = s_neg[tid*5+f];
        }
    }
    __syncthreads();
    if (tid < MAXDET) {
        float c = s_cb[tid*5+4];
        int rank = 0;
        #pragma unroll
        for (int jj = 0; jj < MAXDET; jj++) {
            float cj = s_cb[jj*5+4];
            rank += (cj > c || (cj == c && jj < tid)) ? 1 : 0;
        }
        s_ord[rank] = tid;
    }
    __syncthreads();
    if (tid < MAXDET) {
        int src = s_ord[tid];
        #pragma unroll
        for (int f = 0; f < 5; f++) s_sc[tid*5+f] = s_cb[src*5+f];
    }
    __syncthreads();
    if (tid < MAXDET) {
        float x1 = s_sc[tid*5+0], y1 = s_sc[tid*5+1];
        float x2 = s_sc[tid*5+2], y2 = s_sc[tid*5+3];
        float aa = fmaxf(x2 - x1, 0.f) * fmaxf(y2 - y1, 0.f);
        unsigned m = 0;
        for (int jj = tid + 1; jj < MAXDET; jj++) {
            float ix1 = fmaxf(x1, s_sc[jj*5+0]);
            float iy1 = fmaxf(y1, s_sc[jj*5+1]);
            float ix2 = fminf(x2, s_sc[jj*5+2]);
            float iy2 = fminf(y2, s_sc[jj*5+3]);
            float inter = fmaxf(ix2 - ix1, 0.f) * fmaxf(iy2 - iy1, 0.f);
            if (inter > 0.f) {
                float aj = fmaxf(s_sc[jj*5+2]-s_sc[jj*5+0],0.f) * fmaxf(s_sc[jj*5+3]-s_sc[jj*5+1],0.f);
                float iou = inter / (aa + aj - inter + 1e-9f);
                if (iou > IOU_T) m |= (1u << jj);
            }
        }
        s_supE[tid] = m;
    }
    __syncthreads();
    if (tid == 0) {
        unsigned alive = 0;
        for (int s = 0; s < MAXDET; s++) if (s_sc[s*5+4] > 0.0f) alive |= (1u << s);
        unsigned keepm = 0;
        for (int s = 0; s < MAXDET; s++) {
            if ((alive >> s) & 1u) { keepm |= (1u << s); alive &= ~s_supE[s]; }
        }
        s_keepmask = keepm;
    }
    __syncthreads();
    if (tid < MAXDET) {
        int k2 = (s_keepmask >> tid) & 1;
        int4 r;
        if (k2) {
            r.x = (int)floorf(s_sc[tid*5+0] + 0.5f);
            r.y = (int)floorf(s_sc[tid*5+1] + 0.5f);
            r.z = (int)floorf(s_sc[tid*5+2] + 0.5f);
            r.w = (int)floorf(s_sc[tid*5+3] + 0.5f);
        } else {
            r.x = 0; r.y = 0; r.z = 0; r.w = 0;   // y < r.w never true
        }
        s_rect[tid] = r;
    }
    __syncthreads();

    if (j == 32) {
        // ---- output block: tbox + keep2 ----
        if (tid < MAXDET) {
            int k2 = (s_keepmask >> tid) & 1;
            float* tb = out_tbox + b * (MAXDET * 4);
            #pragma unroll
            for (int f = 0; f < 4; f++)
                tb[tid*4+f] = k2 ? s_sc[tid*5+f] : 0.0f;
            out_keep2[b * MAXDET + tid] = k2 ? 1.0f : 0.0f;
        }
        return;
    }

    // ---- mask slice: 16 rows starting at j*16 ----
    {
        const int base_px = j * (16 * IMG_W);        // 8192 px per slice
        #pragma unroll
        for (int pass = 0; pass < 2; pass++) {
            int t   = base_px + (pass * TB + tid) * 16;
            int y   = t >> 9;
            int x0  = t & (IMG_W - 1);
            unsigned cover = 0;
            #pragma unroll
            for (int s = 0; s < MAXDET; s++) {
                int4 rr = s_rect[s];
                if (y >= rr.y && y < rr.w) {
                    int st = max(rr.x - x0, 0);
                    int en = min(rr.z - x0, 16);
                    if (en > st) cover |= ((1u << en) - (1u << st));
                }
            }
            float m[16];
            #pragma unroll
            for (int c = 0; c < 16; c++) m[c] = (cover >> c & 1u) ? 0.f : 1.f;

            float* dst = out_mask + ((long)b << 18) + t;
            asm volatile("st.global.v8.f32 [%0], {%1,%2,%3,%4,%5,%6,%7,%8};"
                         :: "l"(dst),
                            "f"(m[0]), "f"(m[1]), "f"(m[2]), "f"(m[3]),
                            "f"(m[4]), "f"(m[5]), "f"(m[6]), "f"(m[7]) : "memory");
            asm volatile("st.global.v8.f32 [%0], {%1,%2,%3,%4,%5,%6,%7,%8};"
                         :: "l"(dst + 8),
                            "f"(m[8]),  "f"(m[9]),  "f"(m[10]), "f"(m[11]),
                            "f"(m[12]), "f"(m[13]), "f"(m[14]), "f"(m[15]) : "memory");
        }
    }
}

extern "C" void kernel_launch(void* const* d_in, const int* in_sizes, int n_in,
                              void* d_out, int out_size)
{
    const float* region = nullptr;
    const float* neg    = nullptr;
    for (int i = 0; i < n_in; i++) {
        if (in_sizes[i] == NIMG * NBOX * 5)        region = (const float*)d_in[i];
        else if (in_sizes[i] == NIMG * MAXDET * 5) neg    = (const float*)d_in[i];
    }

    float* out      = (float*)d_out;
    float* out_mask = out;
    float* out_tbox = out + (long)NIMG * IMG_H * IMG_W;
    float* out_k2   = out_tbox + NIMG * MAXDET * 4;

    fused_kernel<<<NIMG * BLK_PER_IMG, TB>>>(region, neg, out_mask, out_tbox, out_k2);
}

// round 16
// speedup vs baseline: 1.7995x; 1.0752x over previous
#include <cuda_runtime.h>

#define NBOX   2000
#define MAXDET 10
#define TOPK   5
#define IMG_H  512
#define IMG_W  512
#define NIMG   16
#define CONF_T 0.2f
#define IOU_T  0.4f
#define FIX_T  0.98f
#define TB     256
#define NCAND  64
#define BLK_PER_IMG 9      // 8 mask-slice blocks (64 rows each) + 1 output block

// per-BLOCK fallback scratch (rare path) — no cross-block races
__device__ unsigned long long g_fbkey[NIMG * BLK_PER_IMG][NBOX];

__device__ __forceinline__ unsigned long long u64max(unsigned long long a, unsigned long long b) {
    return a > b ? a : b;
}

__global__ __launch_bounds__(TB)
void fused_kernel(const float* __restrict__ region,
                  const float* __restrict__ neg,
                  float* __restrict__ out_mask,
                  float* __restrict__ out_tbox,
                  float* __restrict__ out_keep2)
{
    const int bid = blockIdx.x;
    const int b   = bid / BLK_PER_IMG;          // image
    const int j   = bid - b * BLK_PER_IMG;      // 0..7 mask slices, 8 = output block
    const int tid = threadIdx.x;
    const int wid = tid >> 5;
    const int lid = tid & 31;
    const float* rb = region + (long)b * NBOX * 5;

    __shared__ float s_neg[MAXDET * 5];
    __shared__ int s_fb, s_hasconf, s_ncand, s_pcnt;
    __shared__ unsigned long long s_ck[NCAND];
    __shared__ float4 s_cbox[NCAND];
    __shared__ unsigned long long s_skey[NCAND];
    __shared__ float4 s_sbox[NCAND];
    __shared__ unsigned long long s_sup[NCAND];
    __shared__ unsigned char s_tinyb[NCAND];
    __shared__ unsigned long long s_wmax[8];
    __shared__ unsigned long long s_win;
    __shared__ float4 s_pk[MAXDET];
    __shared__ float  s_pkcf[MAXDET];
    __shared__ float s_cb[MAXDET * 5];
    __shared__ int   s_ord[MAXDET];
    __shared__ float s_sc[MAXDET * 5];
    __shared__ unsigned s_supE[MAXDET];
    __shared__ unsigned s_keepmask;
    __shared__ int4 s_rect[MAXDET];

    if (tid == 0) { s_fb = 0; s_hasconf = 0; s_ncand = 0; s_pcnt = 0; }
    if (tid < MAXDET * 5) s_neg[tid] = neg[b * MAXDET * 5 + tid];
    __syncthreads();

    // ---- phase 1: single sweep — compact candidates with conf > FIX_T ----
    {
        int local_has = 0;
        #pragma unroll
        for (int base = 0; base < 2048; base += TB) {
            int i = base + tid;
            if (i < NBOX) {
                float cf = rb[i * 5 + 4];
                if (cf > CONF_T) local_has = 1;
                if (cf > FIX_T) {
                    int p = atomicAdd(&s_ncand, 1);
                    if (p < NCAND) {
                        s_ck[p] = ((unsigned long long)__float_as_uint(cf) << 32)
                                | (unsigned long long)(0xFFFFFFFFu - (unsigned)i);
                        s_cbox[p] = make_float4(rb[i*5+0], rb[i*5+1], rb[i*5+2], rb[i*5+3]);
                    }
                }
            }
        }
        if (local_has) s_hasconf = 1;    // benign race: all writers store 1
    }
    __syncthreads();

    int nc = min(s_ncand, NCAND);

    // ---- phase 2: rank sort (keys distinct -> canonical descending order) ----
    if (tid < NCAND) {
        unsigned long long mykey = (tid < nc) ? s_ck[tid] : 0ULL;
        int rank = 0;
        for (int jj = 0; jj < nc; jj++) rank += (s_ck[jj] > mykey) ? 1 : 0;
        if (tid < nc) {
            s_skey[rank] = mykey;
            float4 bb = s_cbox[tid];
            s_sbox[rank]  = bb;
            s_tinyb[rank] = (bb.z - bb.x >= 1.0f && bb.w - bb.y >= 1.0f) ? 1 : 0;
        }
    }
    __syncthreads();

    // ---- phase 3: suppression matrix in sorted space (ballot rows, div-skip) ----
    for (int t = wid; t < 2 * nc; t += 8) {
        int row = t >> 1, colbase = (t & 1) << 5;
        bool bit = false;
        {
            float4 bi = s_sbox[row];
            float ai = fmaxf(bi.z - bi.x, 0.f) * fmaxf(bi.w - bi.y, 0.f);
            int col = colbase + lid;
            if (col < nc) {
                float4 bj = s_sbox[col];
                float ix1 = fmaxf(bi.x, bj.x), iy1 = fmaxf(bi.y, bj.y);
                float ix2 = fminf(bi.z, bj.z), iy2 = fminf(bi.w, bj.w);
                float inter = fmaxf(ix2 - ix1, 0.f) * fmaxf(iy2 - iy1, 0.f);
                if (inter > 0.f) {
                    float aj  = fmaxf(bj.z - bj.x, 0.f) * fmaxf(bj.w - bj.y, 0.f);
                    float iou = inter / (ai + aj - inter + 1e-9f);
                    bit = (iou > IOU_T);
                }
            }
        }
        unsigned mm = __ballot_sync(0xFFFFFFFFu, bit);
        if (lid == 0) ((unsigned*)s_sup)[t] = mm;
    }
    __syncthreads();

    // ---- phase 4: ffs-driven greedy scan (tid 0) ----
    if (tid == 0) {
        if (s_ncand > NCAND) s_fb = 1;
        else {
            int pcnt = 0;
            unsigned long long alive = (nc >= 64) ? ~0ULL : ((1ULL << nc) - 1ULL);
            while (alive && pcnt < MAXDET) {
                int s = __ffsll((long long)alive) - 1;
                alive &= ~s_sup[s];
                alive &= ~(1ULL << s);
                if (s_tinyb[s]) {
                    s_pk[pcnt]   = s_sbox[s];
                    s_pkcf[pcnt] = __uint_as_float((unsigned)(s_skey[s] >> 32));
                    pcnt++;
                }
            }
            s_pcnt = pcnt;
            if (pcnt < MAXDET) s_fb = 1;   // fixed T never "complete": must fall back
        }
    }
    __syncthreads();

    if (s_fb) {
        // ===== FALLBACK: exact iterative-argmax greedy NMS (per-block global scratch) =====
        const bool  hasconf = (s_hasconf != 0);
        const int   cap  = hasconf ? MAXDET : TOPK;
        const float thr0 = hasconf ? CONF_T : 0.0f;
        unsigned long long* fk = g_fbkey[bid];

        for (int i = tid; i < NBOX; i += TB) {
            float cf = rb[i * 5 + 4];
            fk[i] = (cf > thr0)
                ? (((unsigned long long)__float_as_uint(cf) << 32)
                   | (unsigned long long)(0xFFFFFFFFu - (unsigned)i))
                : 0ULL;
        }
        __syncthreads();

        int   oi  = -1;
        float x1i = -1e9f, y1i = -1e9f, x2i = -1e9f, y2i = -1e9f, ai = 0.0f;
        int   cnt = 0;

        while (true) {
            unsigned long long part = 0ULL;
            for (int jj = tid; jj < NBOX; jj += TB) {
                unsigned long long k = fk[jj];
                if (!k) continue;
                if (jj == oi) { fk[jj] = 0ULL; continue; }
                float x1j = rb[jj*5+0], y1j = rb[jj*5+1];
                float x2j = rb[jj*5+2], y2j = rb[jj*5+3];
                float ix1 = fmaxf(x1i, x1j), iy1 = fmaxf(y1i, y1j);
                float ix2 = fminf(x2i, x2j), iy2 = fminf(y2i, y2j);
                float inter = fmaxf(ix2 - ix1, 0.0f) * fmaxf(iy2 - iy1, 0.0f);
                bool kill = false;
                if (inter > 0.f) {
                    float aj  = fmaxf(x2j - x1j, 0.0f) * fmaxf(y2j - y1j, 0.0f);
                    float iou = inter / (ai + aj - inter + 1e-9f);
                    kill = (iou > IOU_T);
                }
                if (kill) fk[jj] = 0ULL;
                else      part = u64max(part, k);
            }
            #pragma unroll
            for (int off = 16; off; off >>= 1)
                part = u64max(part, __shfl_down_sync(0xFFFFFFFFu, part, off));
            if (lid == 0) s_wmax[wid] = part;
            __syncthreads();
            if (wid == 0) {
                unsigned long long m = (lid < 8) ? s_wmax[lid] : 0ULL;
                #pragma unroll
                for (int off = 4; off; off >>= 1)
                    m = u64max(m, __shfl_down_sync(0xFFFFFFFFu, m, off));
                if (lid == 0) s_win = m;
            }
            __syncthreads();
            unsigned long long win = s_win;
            if (win == 0ULL) break;

            oi = (int)(0xFFFFFFFFu - (unsigned)(win & 0xFFFFFFFFull));
            x1i = rb[oi*5+0]; y1i = rb[oi*5+1];
            x2i = rb[oi*5+2]; y2i = rb[oi*5+3];
            ai = fmaxf(x2i - x1i, 0.0f) * fmaxf(y2i - y1i, 0.0f);
            if (x2i - x1i >= 1.0f && y2i - y1i >= 1.0f) {
                if (tid == 0) {
                    s_pk[cnt]   = make_float4(x1i, y1i, x2i, y2i);
                    s_pkcf[cnt] = __uint_as_float((unsigned)(win >> 32));
                }
                cnt++;
                if (cnt >= cap) break;
            }
        }
        if (tid == 0) s_pcnt = cnt;
        __syncthreads();
    }

    // ============ EPILOGUE: warp 0 only, __syncwarp-internal ============
    if (wid == 0) {
        if (lid < MAXDET) {
            if (lid < s_pcnt) {
                float4 bb = s_pk[lid];
                s_cb[lid*5+0] = bb.x; s_cb[lid*5+1] = bb.y;
                s_cb[lid*5+2] = bb.z; s_cb[lid*5+3] = bb.w;
                s_cb[lid*5+4] = s_pkcf[lid];
            } else {
                #pragma unroll
                for (int f = 0; f < 5; f++) s_cb[lid*5+f] = s_neg[lid*5+f];
            }
        }
        __syncwarp();
        if (lid < MAXDET) {
            float c = s_cb[lid*5+4];
            int rank = 0;
            #pragma unroll
            for (int jj = 0; jj < MAXDET; jj++) {
                float cj = s_cb[jj*5+4];
                rank += (cj > c || (cj == c && jj < lid)) ? 1 : 0;
            }
            s_ord[rank] = lid;
        }
        __syncwarp();
        if (lid < MAXDET) {
            int src = s_ord[lid];
            #pragma unroll
            for (int f = 0; f < 5; f++) s_sc[lid*5+f] = s_cb[src*5+f];
        }
        __syncwarp();
        if (lid < MAXDET) {
            float x1 = s_sc[lid*5+0], y1 = s_sc[lid*5+1];
            float x2 = s_sc[lid*5+2], y2 = s_sc[lid*5+3];
            float aa = fmaxf(x2 - x1, 0.f) * fmaxf(y2 - y1, 0.f);
            unsigned m = 0;
            for (int jj = lid + 1; jj < MAXDET; jj++) {
                float ix1 = fmaxf(x1, s_sc[jj*5+0]);
                float iy1 = fmaxf(y1, s_sc[jj*5+1]);
                float ix2 = fminf(x2, s_sc[jj*5+2]);
                float iy2 = fminf(y2, s_sc[jj*5+3]);
                float inter = fmaxf(ix2 - ix1, 0.f) * fmaxf(iy2 - iy1, 0.f);
                if (inter > 0.f) {
                    float aj = fmaxf(s_sc[jj*5+2]-s_sc[jj*5+0],0.f) * fmaxf(s_sc[jj*5+3]-s_sc[jj*5+1],0.f);
                    float iou = inter / (aa + aj - inter + 1e-9f);
                    if (iou > IOU_T) m |= (1u << jj);
                }
            }
            s_supE[lid] = m;
        }
        __syncwarp();
        if (lid == 0) {
            unsigned alive = 0;
            for (int s = 0; s < MAXDET; s++) if (s_sc[s*5+4] > 0.0f) alive |= (1u << s);
            unsigned keepm = 0;
            for (int s = 0; s < MAXDET; s++) {
                if ((alive >> s) & 1u) { keepm |= (1u << s); alive &= ~s_supE[s]; }
            }
            s_keepmask = keepm;
        }
        __syncwarp();
        if (lid < MAXDET) {
            int k2 = (s_keepmask >> lid) & 1;
            int4 r;
            if (k2) {
                r.x = (int)floorf(s_sc[lid*5+0] + 0.5f);
                r.y = (int)floorf(s_sc[lid*5+1] + 0.5f);
                r.z = (int)floorf(s_sc[lid*5+2] + 0.5f);
                r.w = (int)floorf(s_sc[lid*5+3] + 0.5f);
            } else {
                r.x = 0; r.y = 0; r.z = 0; r.w = 0;   // y < r.w never true
            }
            s_rect[lid] = r;
        }
    }
    __syncthreads();   // publish s_rect / s_keepmask / s_sc to all warps

    if (j == BLK_PER_IMG - 1) {
        // ---- output block: tbox + keep2 ----
        if (tid < MAXDET) {
            int k2 = (s_keepmask >> tid) & 1;
            float* tb = out_tbox + b * (MAXDET * 4);
            #pragma unroll
            for (int f = 0; f < 4; f++)
                tb[tid*4+f] = k2 ? s_sc[tid*5+f] : 0.0f;
            out_keep2[b * MAXDET + tid] = k2 ? 1.0f : 0.0f;
        }
        return;
    }

    // ---- mask slice: 64 rows starting at j*64 (8 passes of 16px groups) ----
    {
        const int base_px = j * (64 * IMG_W);        // 32768 px per slice
        #pragma unroll
        for (int pass = 0; pass < 8; pass++) {
            int t   = base_px + (pass * TB + tid) * 16;
            int y   = t >> 9;
            int x0  = t & (IMG_W - 1);
            unsigned cover = 0;
            #pragma unroll
            for (int s = 0; s < MAXDET; s++) {
                int4 rr = s_rect[s];
                if (y >= rr.y && y < rr.w) {
                    int st = max(rr.x - x0, 0);
                    int en = min(rr.z - x0, 16);
                    if (en > st) cover |= ((1u << en) - (1u << st));
                }
            }
            float m[16];
            #pragma unroll
            for (int c = 0; c < 16; c++) m[c] = (cover >> c & 1u) ? 0.f : 1.f;

            float* dst = out_mask + ((long)b << 18) + t;
            asm volatile("st.global.v8.f32 [%0], {%1,%2,%3,%4,%5,%6,%7,%8};"
                         :: "l"(dst),
                            "f"(m[0]), "f"(m[1]), "f"(m[2]), "f"(m[3]),
                            "f"(m[4]), "f"(m[5]), "f"(m[6]), "f"(m[7]) : "memory");
            asm volatile("st.global.v8.f32 [%0], {%1,%2,%3,%4,%5,%6,%7,%8};"
                         :: "l"(dst + 8),
                            "f"(m[8]),  "f"(m[9]),  "f"(m[10]), "f"(m[11]),
                            "f"(m[12]), "f"(m[13]), "f"(m[14]), "f"(m[15]) : "memory");
        }
    }
}

extern "C" void kernel_launch(void* const* d_in, const int* in_sizes, int n_in,
                              void* d_out, int out_size)
{
    const float* region = nullptr;
    const float* neg    = nullptr;
    for (int i = 0; i < n_in; i++) {
        if (in_sizes[i] == NIMG * NBOX * 5)        region = (const float*)d_in[i];
        else if (in_sizes[i] == NIMG * MAXDET * 5) neg    = (const float*)d_in[i];
    }

    float* out      = (float*)d_out;
    float* out_mask = out;
    float* out_tbox = out + (long)NIMG * IMG_H * IMG_W;
    float* out_k2   = out_tbox + NIMG * MAXDET * 4;

    fused_kernel<<<NIMG * BLK_PER_IMG, TB>>>(region, neg, out_mask, out_tbox, out_k2);
}